// round 16
// baseline (speedup 1.0000x reference)
#include <cuda_runtime.h>
#include <cuda_bf16.h>
#include <math.h>
#include <stdint.h>

#define BATCH    1024
#define DIM      512
#define NCLS     100000
#define NCLS_PAD 100096              // 782 * 128
#define SCALE    64.0f
#define MARGIN   0.5f
#define PI_F     3.14159265358979323846f

#define BM  128
#define BN  128
#define KT  32                        // K per pipeline stage
#define NSTAGE (DIM / KT)             // 16
#define NCHUNK (NCLS_PAD / BN)        // 782

// SMEM layout (per CTA):
//   A bf16 slots:   4 x 8192  = 32768
//   B f32  slots:   4 x 16384 = 65536
//   B bf16 buffer:  1 x 8192
//   inv_w:          512
#define SM_A      0
#define SM_BF32   32768
#define SM_BB16   98304
#define SM_INVW   106496
#define SM_TOTAL  107008

// ---------------- device scratch (no allocation allowed) -------------------
__device__ __nv_bfloat16 g_ebf[BATCH * DIM];   // normalized embeddings (bf16)
__device__ float g_inv_e[BATCH];
__device__ float g_pmax[BATCH * NCHUNK];
__device__ float g_psum[BATCH * NCHUNK];
__device__ float g_part[BATCH / 8];            // per-tail-block partial sums
__device__ int   g_done;                       // tail completion counter

// ---------------- PTX helpers (compute_103-safe: sm_80-era ops) -------------
__device__ __forceinline__ uint32_t smem_u32(const void* p) {
    uint32_t a;
    asm("{ .reg .u64 t; cvta.to.shared.u64 t, %1; cvt.u32.u64 %0, t; }" : "=r"(a) : "l"(p));
    return a;
}

__device__ __forceinline__ void cp_async16(uint32_t dst, const void* src) {
    asm volatile("cp.async.cg.shared.global [%0], [%1], 16;" :: "r"(dst), "l"(src));
}
#define CP_COMMIT() asm volatile("cp.async.commit_group;" ::: "memory")
#define CP_WAIT(n)  asm volatile("cp.async.wait_group %0;" :: "n"(n) : "memory")

__device__ __forceinline__ void ldsm_x4(uint32_t& r0, uint32_t& r1,
                                        uint32_t& r2, uint32_t& r3, uint32_t addr) {
    asm volatile("ldmatrix.sync.aligned.m8n8.x4.shared.b16 {%0,%1,%2,%3}, [%4];"
                 : "=r"(r0), "=r"(r1), "=r"(r2), "=r"(r3) : "r"(addr));
}

__device__ __forceinline__ void mma_bf16(float* c,
                                         uint32_t a0, uint32_t a1, uint32_t a2, uint32_t a3,
                                         uint32_t b0, uint32_t b1) {
    asm volatile(
        "mma.sync.aligned.m16n8k16.row.col.f32.bf16.bf16.f32 "
        "{%0,%1,%2,%3}, {%4,%5,%6,%7}, {%8,%9}, {%0,%1,%2,%3};"
        : "+f"(c[0]), "+f"(c[1]), "+f"(c[2]), "+f"(c[3])
        : "r"(a0), "r"(a1), "r"(a2), "r"(a3), "r"(b0), "r"(b1));
}

// bf16 tile swizzle: 64B rows of 4x16B chunks, chunk' = chunk ^ ((row>>1)&3).
__device__ __forceinline__ uint32_t sw_off(int row, int chunk) {
    return (uint32_t)(row * 64 + ((chunk ^ ((row >> 1) & 3)) << 4));
}
// f32 tile swizzle: 128B rows of 8x16B chunks, chunk' = chunk ^ (row&7).
__device__ __forceinline__ uint32_t sw_off32(int row, int chunk) {
    return (uint32_t)(row * 128 + ((chunk ^ (row & 7)) << 4));
}

// ---------------------------------------------------------------------------
// Kernel 1: prep embeddings — normalize + bf16 convert. One warp/row.
// Block 0 also resets the tail completion counter.
// ---------------------------------------------------------------------------
__global__ void prep_kernel(const float* __restrict__ emb) {
    if (blockIdx.x == 0 && threadIdx.x == 0) g_done = 0;
    int row  = blockIdx.x * 8 + (threadIdx.x >> 5);
    int lane = threadIdx.x & 31;
    if (row >= BATCH) return;

    const float4* p = (const float4*)(emb + (size_t)row * DIM);
    float4 v[4];
    float s = 0.f;
#pragma unroll
    for (int i = 0; i < 4; i++) {
        v[i] = p[lane + i * 32];
        s = fmaf(v[i].x, v[i].x, s);
        s = fmaf(v[i].y, v[i].y, s);
        s = fmaf(v[i].z, v[i].z, s);
        s = fmaf(v[i].w, v[i].w, s);
    }
#pragma unroll
    for (int o = 16; o; o >>= 1) s += __shfl_xor_sync(0xFFFFFFFFu, s, o);
    float inv = rsqrtf(s);
    if (lane == 0) g_inv_e[row] = inv;

    __nv_bfloat16* dst = &g_ebf[(size_t)row * DIM];
#pragma unroll
    for (int i = 0; i < 4; i++) {
        __nv_bfloat162 lo = __floats2bfloat162_rn(v[i].x * inv, v[i].y * inv);
        __nv_bfloat162 hi = __floats2bfloat162_rn(v[i].z * inv, v[i].w * inv);
        uint2 pk;
        pk.x = *(uint32_t*)&lo;
        pk.y = *(uint32_t*)&hi;
        ((uint2*)dst)[lane + i * 32] = pk;
    }
}

// ---------------------------------------------------------------------------
// Kernel 2: bf16 mma.sync GEMM 128x128x512.
//  A: normalized bf16 via cp.async (4-deep).
//  B: f32 weights via cp.async into SMEM (4-deep); converted SMEM->SMEM to a
//     single bf16 buffer at stage start; per-thread ssq accumulates the W row
//     norms -> inv_w in SMEM -> applied in epilogue. No W scratch in DRAM.
//  Grid: x = row-block (8, fast), y = chunk (782) => f32 W tile L2-resident.
// ---------------------------------------------------------------------------
__device__ __forceinline__ void issue_stage(uint32_t smem_base, int sbuf,
                                            const float* __restrict__ wgt,
                                            int rowBase, int colBase, int kBase, int tid) {
    const uint32_t aBase = smem_base + SM_A + sbuf * 8192;
#pragma unroll
    for (int i = 0; i < 2; i++) {          // A: 128 rows x 4 x 16B
        int idx = tid + i * 256;
        int r = idx >> 2, c = idx & 3;
        cp_async16(aBase + sw_off(r, c),
                   &g_ebf[(size_t)(rowBase + r) * DIM + kBase + c * 8]);
    }
    const uint32_t bBase = smem_base + SM_BF32 + sbuf * 16384;
#pragma unroll
    for (int i = 0; i < 4; i++) {          // B f32: 128 rows x 8 x 16B
        int idx = tid + i * 256;
        int r = idx >> 3, c = idx & 7;
        int gr = colBase + r;
        uint32_t dst = bBase + sw_off32(r, c);
        if (gr < NCLS) {
            cp_async16(dst, wgt + (size_t)gr * DIM + kBase + c * 4);
        } else {
            uint4 z = make_uint4(0u, 0u, 0u, 0u);
            *(uint4*)((char*)0 + 0 + (size_t)0, (uint4*)0) = z;  // placeholder
        }
    }
}

__global__ __launch_bounds__(256, 2)
void gemm_mma_kernel(const float* __restrict__ wgt) {
    extern __shared__ __align__(16) char smem[];
    const uint32_t smem_base = smem_u32(smem);
    const int tid  = threadIdx.x;
    const int wid  = tid >> 5;
    const int lane = tid & 31;
    const int wr   = wid >> 2;           // 0..1  (m)
    const int wc   = wid & 3;            // 0..3  (n)
    const int chunk   = blockIdx.y;
    const int rowBase = blockIdx.x * BM;
    const int colBase = chunk * BN;
    const bool lastChunk = (chunk == NCHUNK - 1);

    // zero-fill the f32 B slots once if this chunk has pad rows (simple, rare)
    if (lastChunk) {
        for (int i = tid; i < 4 * 16384 / 16; i += 256)
            *(uint4*)(smem + SM_BF32 + i * 16) = make_uint4(0u, 0u, 0u, 0u);
        __syncthreads();
    }

    // convert-pass assignment: row cr = tid>>1, k-half ch = tid&1 (stage-invariant)
    const int cr = tid >> 1;
    const int ch = tid & 1;
    float ssq = 0.f;

    // per-lane ldmatrix row components
    const int r_in = lane & 7;
    const int a_row_base = wr * 64 + ((lane >> 3) & 1) * 8 + r_in;
    const int a_chunk    = (lane >> 4);          // + ks*2
    const int b_row_base = wc * 32 + (lane >> 4) * 8 + r_in;
    const int b_chunk    = ((lane >> 3) & 1);    // + ks*2

    float acc[4][4][4];
#pragma unroll
    for (int i = 0; i < 4; i++)
#pragma unroll
        for (int j = 0; j < 4; j++)
#pragma unroll
            for (int k = 0; k < 4; k++) acc[i][j][k] = 0.f;

    // ---- issue helper (A bf16 + B f32), pad rows skipped (pre-zeroed) -----
#define ISSUE(sbuf, kBase) do {                                               \
    const uint32_t aB = smem_base + SM_A + (sbuf) * 8192;                     \
    _Pragma("unroll")                                                         \
    for (int i = 0; i < 2; i++) {                                             \
        int idx = tid + i * 256;                                              \
        int r = idx >> 2, c = idx & 3;                                        \
        cp_async16(aB + sw_off(r, c),                                         \
                   &g_ebf[(size_t)(rowBase + r) * DIM + (kBase) + c * 8]);    \
    }                                                                         \
    const uint32_t bB = smem_base + SM_BF32 + (sbuf) * 16384;                 \
    _Pragma("unroll")                                                         \
    for (int i = 0; i < 4; i++) {                                             \
        int idx = tid + i * 256;                                              \
        int r = idx >> 3, c = idx & 7;                                        \
        int gr = colBase + r;                                                 \
        if (gr < NCLS)                                                        \
            cp_async16(bB + sw_off32(r, c),                                   \
                       wgt + (size_t)gr * DIM + (kBase) + c * 4);             \
    }                                                                         \
} while (0)

    // prologue: stages 0..2 in flight
    ISSUE(0, 0 * KT); CP_COMMIT();
    ISSUE(1, 1 * KT); CP_COMMIT();
    ISSUE(2, 2 * KT); CP_COMMIT();

#pragma unroll
    for (int kt = 0; kt < NSTAGE; kt++) {
        CP_WAIT(2);                      // stage kt resident; kt+1, kt+2 in flight
        __syncthreads();                 // f32 B visible; prior LDSMs done

        // ---- convert B f32 -> bf16 (SMEM->SMEM) + ssq ----------------------
        {
            const uint32_t bf = smem_base + SM_BF32 + (kt & 3) * 16384;
            const uint32_t bb = smem_base + SM_BB16;
#pragma unroll
            for (int j = 0; j < 2; j++) {         // two 16B-bf16 outputs
                int c0 = ch * 4 + j * 2;          // two f32 chunks per output
                uint4 u0 = *(uint4*)(smem + SM_BF32 + (kt & 3) * 16384 + sw_off32(cr, c0));
                uint4 u1 = *(uint4*)(smem + SM_BF32 + (kt & 3) * 16384 + sw_off32(cr, c0 + 1));
                float f0 = __uint_as_float(u0.x), f1 = __uint_as_float(u0.y);
                float f2 = __uint_as_float(u0.z), f3 = __uint_as_float(u0.w);
                float f4 = __uint_as_float(u1.x), f5 = __uint_as_float(u1.y);
                float f6 = __uint_as_float(u1.z), f7 = __uint_as_float(u1.w);
                ssq = fmaf(f0, f0, ssq); ssq = fmaf(f1, f1, ssq);
                ssq = fmaf(f2, f2, ssq); ssq = fmaf(f3, f3, ssq);
                ssq = fmaf(f4, f4, ssq); ssq = fmaf(f5, f5, ssq);
                ssq = fmaf(f6, f6, ssq); ssq = fmaf(f7, f7, ssq);
                __nv_bfloat162 p0 = __floats2bfloat162_rn(f0, f1);
                __nv_bfloat162 p1 = __floats2bfloat162_rn(f2, f3);
                __nv_bfloat162 p2 = __floats2bfloat162_rn(f4, f5);
                __nv_bfloat162 p3 = __floats2bfloat162_rn(f6, f7);
                uint4 pk;
                pk.x = *(uint32_t*)&p0; pk.y = *(uint32_t*)&p1;
                pk.z = *(uint32_t*)&p2; pk.w = *(uint32_t*)&p3;
                *(uint4*)(smem + SM_BB16 + sw_off(cr, ch * 2 + j)) = pk;
            }
            (void)bf; (void)bb;
        }
        __syncthreads();                 // bf16 B ready for LDSM

        const uint32_t aBase = smem_base + SM_A + (kt & 3) * 8192;
        const uint32_t bBase = smem_base + SM_BB16;
#pragma unroll
        for (int ks = 0; ks < 2; ks++) {
            uint32_t af[4][4];
#pragma unroll
            for (int mi = 0; mi < 4; mi++) {
                int row = a_row_base + mi * 16;
                ldsm_x4(af[mi][0], af[mi][1], af[mi][2], af[mi][3],
                        aBase + sw_off(row, ks * 2 + a_chunk));
            }
            uint32_t bfr[4][2];
#pragma unroll
            for (int nb = 0; nb < 2; nb++) {
                int row = b_row_base + nb * 16;
                uint32_t r0, r1, r2, r3;
                ldsm_x4(r0, r1, r2, r3, bBase + sw_off(row, ks * 2 + b_chunk));
                bfr[nb * 2 + 0][0] = r0; bfr[nb * 2 + 0][1] = r1;
                bfr[nb * 2 + 1][0] = r2; bfr[nb * 2 + 1][1] = r3;
            }
#pragma unroll
            for (int mi = 0; mi < 4; mi++)
#pragma unroll
                for (int ni = 0; ni < 4; ni++)
                    mma_bf16(acc[mi][ni], af[mi][0], af[mi][1], af[mi][2], af[mi][3],
                             bfr[ni][0], bfr[ni][1]);
        }

        // refill slot consumed at stage kt-1
        if (kt + 3 < NSTAGE)
            ISSUE((kt + 3) & 3, (kt + 3) * KT);
        CP_COMMIT();
    }
#undef ISSUE

    // ---- inv_w: combine the two half-row ssq's (adjacent lanes) ------------
    ssq += __shfl_xor_sync(0xFFFFFFFFu, ssq, 1);
    float* invw_sm = (float*)(smem + SM_INVW);
    if (ch == 0) invw_sm[cr] = (ssq > 0.f) ? rsqrtf(ssq) : 0.f;
    __syncthreads();   // invw visible; stage buffers dead -> 'red' may reuse

    // ---- epilogue: scale by inv_w, clip*64, per-row (max,sumexp) -----------
    const int gid = lane >> 2;
    const int tg  = lane & 3;
    float2* red = (float2*)smem;            // [128][4], reuses stage SMEM

    float invw8[8];
#pragma unroll
    for (int ni = 0; ni < 4; ni++)
#pragma unroll
        for (int c = 0; c < 2; c++)
            invw8[ni * 2 + c] = invw_sm[wc * 32 + ni * 8 + tg * 2 + c];

#pragma unroll
    for (int mi = 0; mi < 4; mi++) {
#pragma unroll
        for (int h = 0; h < 2; h++) {
            const int rloc = wr * 64 + mi * 16 + h * 8 + gid;
            float vv[8];
            bool  okk[8];
            float lm = -1e30f;
#pragma unroll
            for (int ni = 0; ni < 4; ni++) {
#pragma unroll
                for (int c = 0; c < 2; c++) {
                    int n = wc * 32 + ni * 8 + tg * 2 + c;
                    float v = acc[mi][ni][h * 2 + c] * invw8[ni * 2 + c];
                    v = fminf(1.f, fmaxf(-1.f, v)) * SCALE;
                    bool ok = (colBase + n) < NCLS;
                    vv[ni * 2 + c] = v;
                    okk[ni * 2 + c] = ok;
                    if (ok) lm = fmaxf(lm, v);
                }
            }
            // quad max first (no exps)
#pragma unroll
            for (int o = 1; o <= 2; o <<= 1)
                lm = fmaxf(lm, __shfl_xor_sync(0xFFFFFFFFu, lm, o));
            // single exp pass against final max
            float ls = 0.f;
#pragma unroll
            for (int j = 0; j < 8; j++)
                if (okk[j]) ls += __expf(vv[j] - lm);
            // quad sum
#pragma unroll
            for (int o = 1; o <= 2; o <<= 1)
                ls += __shfl_xor_sync(0xFFFFFFFFu, ls, o);
            if (tg == 0) red[rloc * 4 + wc] = make_float2(lm, ls);
        }
    }
    __syncthreads();

    if (tid < BM) {
        float m = -1e30f, s = 0.f;
#pragma unroll
        for (int w = 0; w < 4; w++) {
            float2 p = red[tid * 4 + w];
            float mn = fmaxf(m, p.x);
            s = s * __expf(m - mn) + p.y * __expf(p.x - mn);
            m = mn;
        }
        g_pmax[(size_t)(rowBase + tid) * NCHUNK + chunk] = m;
        g_psum[(size_t)(rowBase + tid) * NCHUNK + chunk] = s;
    }
}

// ---------------------------------------------------------------------------
// Kernel 3: fused detect + target + LSE + final mean. One warp per row;
// W[label] norm computed inline (fp32-exact). Last block reduces partials.
// ---------------------------------------------------------------------------
__global__ void tail_kernel(const float* __restrict__ emb,
                            const float* __restrict__ wgt,
                            const void* __restrict__ lbl,
                            float* __restrict__ out) {
    __shared__ float sh[8];
    __shared__ int   lastFlag;

    // label dtype detection: 256 threads sample first 2KB (in-bounds for both)
    long long probe = ((const long long*)lbl)[threadIdx.x];
    int ok = (probe >= 0 && probe < (long long)NCLS) ? 1 : 0;
    int is64 = __syncthreads_and(ok);

    int wid  = threadIdx.x >> 5;
    int lane = threadIdx.x & 31;
    int row  = blockIdx.x * 8 + wid;

    long long lab = is64 ? ((const long long*)lbl)[row]
                         : (long long)((const int*)lbl)[row];

    // fp32-exact target dot + W-row sum of squares
    const float4* e4 = (const float4*)(emb + (size_t)row * DIM);
    const float4* w4 = (const float4*)(wgt + (size_t)lab * DIM);
    float td = 0.f, sw = 0.f;
#pragma unroll
    for (int i = 0; i < 4; i++) {
        float4 a = e4[lane + i * 32];
        float4 b = w4[lane + i * 32];
        td = fmaf(a.x, b.x, td);
        td = fmaf(a.y, b.y, td);
        td = fmaf(a.z, b.z, td);
        td = fmaf(a.w, b.w, td);
        sw = fmaf(b.x, b.x, sw);
        sw = fmaf(b.y, b.y, sw);
        sw = fmaf(b.z, b.z, sw);
        sw = fmaf(b.w, b.w, sw);
    }
#pragma unroll
    for (int o = 16; o; o >>= 1) {
        td += __shfl_xor_sync(0xFFFFFFFFu, td, o);
        sw += __shfl_xor_sync(0xFFFFFFFFu, sw, o);
    }

    // LSE merge over chunk partials
    float m = -1e30f, s = 0.f;
    const float* pm_base = &g_pmax[(size_t)row * NCHUNK];
    const float* ps_base = &g_psum[(size_t)row * NCHUNK];
    for (int ch = lane; ch < NCHUNK; ch += 32) {
        float pm = pm_base[ch];
        float ps = ps_base[ch];
        float mn = fmaxf(m, pm);
        s = s * __expf(m - mn) + ps * __expf(pm - mn);
        m = mn;
    }
#pragma unroll
    for (int o = 16; o; o >>= 1) {
        float om = __shfl_xor_sync(0xFFFFFFFFu, m, o);
        float os = __shfl_xor_sync(0xFFFFFFFFu, s, o);
        float mn = fmaxf(m, om);
        s = s * __expf(m - mn) + os * __expf(om - mn);
        m = mn;
    }

    if (lane == 0) {
        float t = td * g_inv_e[row] * rsqrtf(sw);
        t = fminf(1.f, fmaxf(-1.f, t));
        float th = acosf(t);
        float tn = cosf(fminf(th + MARGIN, PI_F)) * SCALE;
        float to = t * SCALE;
        float s2 = s + __expf(tn - m) - __expf(to - m);
        s2 = fmaxf(s2, 1e-30f);
        sh[wid] = m + logf(s2) - tn;
    }
    __syncthreads();

    if (threadIdx.x == 0) {
        float ps = 0.f;
#pragma unroll
        for (int i = 0; i < 8; i++) ps += sh[i];
        g_part[blockIdx.x] = ps;
        __threadfence();
        int prev = atomicAdd(&g_done, 1);
        lastFlag = (prev == (BATCH / 8) - 1) ? 1 : 0;
    }
    __syncthreads();

    if (lastFlag && threadIdx.x == 0) {
        float total = 0.f;
        for (int i = 0; i < BATCH / 8; i++) total += g_part[i];   // fixed order
        out[0] = total / (float)BATCH;
    }
}

// ---------------------------------------------------------------------------
extern "C" void kernel_launch(void* const* d_in, const int* in_sizes, int n_in,
                              void* d_out, int out_size) {
    (void)in_sizes; (void)n_in; (void)out_size;
    const float* emb = (const float*)d_in[0];
    const float* wgt = (const float*)d_in[1];
    const void*  lbl = d_in[2];
    float* out       = (float*)d_out;

    cudaFuncSetAttribute(gemm_mma_kernel,
                         cudaFuncAttributeMaxDynamicSharedMemorySize, SM_TOTAL);

    prep_kernel<<<BATCH / 8, 256>>>(emb);

    dim3 grid(BATCH / BM, NCHUNK);   // x = row-block (fast), y = chunk
    gemm_mma_kernel<<<grid, 256, SM_TOTAL>>>(wgt);

    tail_kernel<<<BATCH / 8, 256>>>(emb, wgt, lbl, out);
}

// round 17
// speedup vs baseline: 1.4397x; 1.4397x over previous
#include <cuda_runtime.h>
#include <cuda_bf16.h>
#include <math.h>
#include <stdint.h>

#define BATCH    1024
#define DIM      512
#define NCLS     100000
#define NCLS_PAD 100096              // 782 * 128
#define SCALE    64.0f
#define MARGIN   0.5f
#define PI_F     3.14159265358979323846f

#define BM  128
#define BN  128
#define KT  64                        // K per pipeline stage
#define NSTAGE (DIM / KT)             // 8
#define NCHUNK (NCLS_PAD / BN)        // 782
#define LA  64                        // prep lookahead (chunks)

#define STAGE_BYTES 32768             // A 16KB + B 16KB per slot
#define SM_TOTAL (3 * STAGE_BYTES)    // 98304 (occupancy 2: 2x96KB <= 228KB)

// ---------------- device scratch (no allocation allowed) -------------------
__device__ __nv_bfloat16 g_ebf[BATCH * DIM];       // normalized embeddings
__device__ __nv_bfloat16 g_wbf[NCLS_PAD * DIM];    // normalized weights (padded zero)
__device__ float g_inv_e[BATCH];
__device__ float g_inv_w[NCLS];
__device__ float g_pmax[BATCH * NCHUNK];
__device__ float g_psum[BATCH * NCHUNK];
__device__ float g_part[BATCH / 8];                // per-tail-block partial sums
__device__ int   g_flag[NCHUNK];                   // per-chunk "W prepped" flag
__device__ int   g_done;                           // tail completion counter

// ---------------- PTX helpers (compute_103-safe: sm_80-era ops) -------------
__device__ __forceinline__ uint32_t smem_u32(const void* p) {
    uint32_t a;
    asm("{ .reg .u64 t; cvta.to.shared.u64 t, %1; cvt.u32.u64 %0, t; }" : "=r"(a) : "l"(p));
    return a;
}

__device__ __forceinline__ void cp_async16(uint32_t dst, const void* src) {
    asm volatile("cp.async.cg.shared.global [%0], [%1], 16;" :: "r"(dst), "l"(src));
}
#define CP_COMMIT() asm volatile("cp.async.commit_group;" ::: "memory")
#define CP_WAIT(n)  asm volatile("cp.async.wait_group %0;" :: "n"(n) : "memory")

__device__ __forceinline__ void ldsm_x4(uint32_t& r0, uint32_t& r1,
                                        uint32_t& r2, uint32_t& r3, uint32_t addr) {
    asm volatile("ldmatrix.sync.aligned.m8n8.x4.shared.b16 {%0,%1,%2,%3}, [%4];"
                 : "=r"(r0), "=r"(r1), "=r"(r2), "=r"(r3) : "r"(addr));
}

__device__ __forceinline__ void mma_bf16(float* c,
                                         uint32_t a0, uint32_t a1, uint32_t a2, uint32_t a3,
                                         uint32_t b0, uint32_t b1) {
    asm volatile(
        "mma.sync.aligned.m16n8k16.row.col.f32.bf16.bf16.f32 "
        "{%0,%1,%2,%3}, {%4,%5,%6,%7}, {%8,%9}, {%0,%1,%2,%3};"
        : "+f"(c[0]), "+f"(c[1]), "+f"(c[2]), "+f"(c[3])
        : "r"(a0), "r"(a1), "r"(a2), "r"(a3), "r"(b0), "r"(b1));
}

// Stage-tile swizzle: 128B rows of 8x16B chunks, chunk' = chunk ^ (row & 7).
// 8 consecutive rows at a fixed chunk hit 8 distinct 16B bank slots
// (conflict-free ldmatrix phases); cp.async dsts stay 16B-aligned.
__device__ __forceinline__ uint32_t sw_off(int row, int chunk) {
    return (uint32_t)(row * 128 + ((chunk ^ (row & 7)) << 4));
}

// ---------------------------------------------------------------------------
// normalize one f32 row -> bf16 row (warp-cooperative), returns inv-norm
// ---------------------------------------------------------------------------
__device__ __forceinline__ float norm_row_to_bf16(const float* __restrict__ src,
                                                  __nv_bfloat16* __restrict__ dst,
                                                  int lane) {
    const float4* p = (const float4*)src;
    float4 v[4];
    float s = 0.f;
#pragma unroll
    for (int i = 0; i < 4; i++) {
        v[i] = p[lane + i * 32];
        s = fmaf(v[i].x, v[i].x, s);
        s = fmaf(v[i].y, v[i].y, s);
        s = fmaf(v[i].z, v[i].z, s);
        s = fmaf(v[i].w, v[i].w, s);
    }
#pragma unroll
    for (int o = 16; o; o >>= 1) s += __shfl_xor_sync(0xFFFFFFFFu, s, o);
    float inv = rsqrtf(s);
#pragma unroll
    for (int i = 0; i < 4; i++) {
        __nv_bfloat162 lo = __floats2bfloat162_rn(v[i].x * inv, v[i].y * inv);
        __nv_bfloat162 hi = __floats2bfloat162_rn(v[i].z * inv, v[i].w * inv);
        uint2 pk;
        pk.x = *(uint32_t*)&lo;
        pk.y = *(uint32_t*)&hi;
        ((uint2*)dst)[lane + i * 32] = pk;
    }
    return inv;
}

// ---------------------------------------------------------------------------
// Kernel 1: initial prep — embeddings + first LA chunks of W. One warp/row.
// Block 0 also resets per-call state (flags, done counter).
// ---------------------------------------------------------------------------
__global__ void prep_kernel(const float* __restrict__ emb,
                            const float* __restrict__ wgt) {
    if (blockIdx.x == 0) {
        for (int i = threadIdx.x; i < NCHUNK; i += 256) g_flag[i] = 0;
        if (threadIdx.x == 0) g_done = 0;
    }
    int row  = blockIdx.x * 8 + (threadIdx.x >> 5);
    int lane = threadIdx.x & 31;

    if (row < BATCH) {
        float inv = norm_row_to_bf16(emb + (size_t)row * DIM,
                                     &g_ebf[(size_t)row * DIM], lane);
        if (lane == 0) g_inv_e[row] = inv;
    } else {
        int r = row - BATCH;
        if (r >= LA * BN) return;       // only first LA chunks here (all < NCLS)
        float inv = norm_row_to_bf16(wgt + (size_t)r * DIM,
                                     &g_wbf[(size_t)r * DIM], lane);
        if (lane == 0) g_inv_w[r] = inv;
    }
}

// ---------------------------------------------------------------------------
// Kernel 2: bf16 mma.sync GEMM 128x128x512, cp.async 3-slot pipeline (KT=64),
// + distributed W-prep with LA-chunk lookahead + per-chunk softmax partials.
// 8 warps (2 m x 4 n), warp tile 64x32, occupancy 2.
// Grid: x = row-block (8, fast), y = chunk (782).
// ---------------------------------------------------------------------------
__device__ __forceinline__ void prep_chunk(const float* __restrict__ wgt,
                                           int pchunk, int tid) {
    const int wid = tid >> 5, lane = tid & 31;
    const int base = pchunk * BN;
#pragma unroll 1
    for (int i = 0; i < 16; i++) {
        int r = base + wid * 16 + i;
        __nv_bfloat16* dst = &g_wbf[(size_t)r * DIM];
        if (r >= NCLS) {                 // pad rows: zero
            uint2 z = make_uint2(0u, 0u);
#pragma unroll
            for (int j = 0; j < 4; j++) ((uint2*)dst)[lane + j * 32] = z;
            continue;
        }
        float inv = norm_row_to_bf16(wgt + (size_t)r * DIM, dst, lane);
        if (lane == 0) g_inv_w[r] = inv;
    }
    __threadfence();                      // release all threads' writes
    __syncthreads();
    if (tid == 0) atomicExch(&g_flag[pchunk], 1);
}

__device__ __forceinline__ void issue_stage(uint32_t smem_base, int sbuf,
                                            int rowBase, int colBase, int kBase, int tid) {
    const uint32_t aBase = smem_base + sbuf * STAGE_BYTES;
    const uint32_t bBase = aBase + 16384;
#pragma unroll
    for (int i = 0; i < 4; i++) {
        int idx = tid + i * 256;          // 0..1023
        int r = idx >> 3;                  // 0..127
        int c = idx & 7;                   // 16B chunk within 128B row
        uint32_t off = sw_off(r, c);
        cp_async16(aBase + off, &g_ebf[(size_t)(rowBase + r) * DIM + kBase + c * 8]);
        cp_async16(bBase + off, &g_wbf[(size_t)(colBase + r) * DIM + kBase + c * 8]);
    }
}

__global__ __launch_bounds__(256, 2)
void gemm_mma_kernel(const float* __restrict__ wgt) {
    extern __shared__ __align__(16) char smem[];
    const uint32_t smem_base = smem_u32(smem);
    const int tid  = threadIdx.x;
    const int wid  = tid >> 5;
    const int lane = tid & 31;
    const int wr   = wid >> 2;           // 0..1  (m)
    const int wc   = wid & 3;            // 0..3  (n)
    const int chunk   = blockIdx.y;
    const int rowBase = blockIdx.x * BM;
    const int colBase = chunk * BN;

    // ---- distributed W-prep: x==0 CTA preps chunk (chunk+LA) --------------
    if (blockIdx.x == 0 && chunk + LA < NCHUNK)
        prep_chunk(wgt, chunk + LA, tid);

    // ---- wait for this chunk's W tile (chunks < LA prepped by prep_kernel) -
    if (chunk >= LA) {
        if (tid == 0) {
            while (atomicOr(&g_flag[chunk], 0) == 0) __nanosleep(64);
            __threadfence();              // acquire
        }
        __syncthreads();
    }

    // per-lane ldmatrix row components
    const int r_in = lane & 7;
    const int a_row_base = wr * 64 + ((lane >> 3) & 1) * 8 + r_in;
    const int a_chunk    = (lane >> 4);          // + ks*2
    const int b_row_base = wc * 32 + (lane >> 4) * 8 + r_in;
    const int b_chunk    = ((lane >> 3) & 1);    // + ks*2

    float acc[4][4][4];
#pragma unroll
    for (int i = 0; i < 4; i++)
#pragma unroll
        for (int j = 0; j < 4; j++)
#pragma unroll
            for (int k = 0; k < 4; k++) acc[i][j][k] = 0.f;

    // prologue: stages 0..1 in flight (3-slot ring)
    issue_stage(smem_base, 0, rowBase, colBase, 0 * KT, tid); CP_COMMIT();
    issue_stage(smem_base, 1, rowBase, colBase, 1 * KT, tid); CP_COMMIT();

#pragma unroll
    for (int kt = 0; kt < NSTAGE; kt++) {
        CP_WAIT(1);                      // stage kt resident; kt+1 in flight
        __syncthreads();

        const int sbuf = kt % 3;
        const uint32_t aBase = smem_base + sbuf * STAGE_BYTES;
        const uint32_t bBase = aBase + 16384;
#pragma unroll
        for (int ks = 0; ks < 4; ks++) {
            uint32_t af[4][4];
#pragma unroll
            for (int mi = 0; mi < 4; mi++) {
                int row = a_row_base + mi * 16;
                ldsm_x4(af[mi][0], af[mi][1], af[mi][2], af[mi][3],
                        aBase + sw_off(row, ks * 2 + a_chunk));
            }
            uint32_t bfr[4][2];
#pragma unroll
            for (int nb = 0; nb < 2; nb++) {
                int row = b_row_base + nb * 16;
                uint32_t r0, r1, r2, r3;
                ldsm_x4(r0, r1, r2, r3, bBase + sw_off(row, ks * 2 + b_chunk));
                bfr[nb * 2 + 0][0] = r0; bfr[nb * 2 + 0][1] = r1;
                bfr[nb * 2 + 1][0] = r2; bfr[nb * 2 + 1][1] = r3;
            }
#pragma unroll
            for (int mi = 0; mi < 4; mi++)
#pragma unroll
                for (int ni = 0; ni < 4; ni++)
                    mma_bf16(acc[mi][ni], af[mi][0], af[mi][1], af[mi][2], af[mi][3],
                             bfr[ni][0], bfr[ni][1]);
        }

        // refill the slot consumed at iteration kt-1 (distinct from kt, kt+1 mod 3)
        if (kt + 2 < NSTAGE)
            issue_stage(smem_base, (kt + 2) % 3, rowBase, colBase, (kt + 2) * KT, tid);
        CP_COMMIT();
    }
    __syncthreads();   // before SMEM reuse by the reduction

    // ---- epilogue: clip*64, per-row (max, sumexp) over this 128-col chunk --
    // max-first: quad-max via pure fmaxf shuffles, ONE exp pass, quad-sum.
    const int gid = lane >> 2;
    const int tg  = lane & 3;
    float2* red = (float2*)smem;            // [128][4]

#pragma unroll
    for (int mi = 0; mi < 4; mi++) {
#pragma unroll
        for (int h = 0; h < 2; h++) {
            const int rloc = wr * 64 + mi * 16 + h * 8 + gid;
            float vv[8];
            bool  okk[8];
            float lm = -1e30f;
#pragma unroll
            for (int ni = 0; ni < 4; ni++) {
#pragma unroll
                for (int c = 0; c < 2; c++) {
                    int n = wc * 32 + ni * 8 + tg * 2 + c;
                    float v = acc[mi][ni][h * 2 + c];
                    v = fminf(1.f, fmaxf(-1.f, v)) * SCALE;
                    bool ok = (colBase + n) < NCLS;
                    vv[ni * 2 + c] = v;
                    okk[ni * 2 + c] = ok;
                    if (ok) lm = fmaxf(lm, v);
                }
            }
#pragma unroll
            for (int o = 1; o <= 2; o <<= 1)
                lm = fmaxf(lm, __shfl_xor_sync(0xFFFFFFFFu, lm, o));
            float ls = 0.f;
#pragma unroll
            for (int j = 0; j < 8; j++)
                if (okk[j]) ls += __expf(vv[j] - lm);
#pragma unroll
            for (int o = 1; o <= 2; o <<= 1)
                ls += __shfl_xor_sync(0xFFFFFFFFu, ls, o);
            if (tg == 0) red[rloc * 4 + wc] = make_float2(lm, ls);
        }
    }
    __syncthreads();

    if (tid < BM) {
        float m = -1e30f, s = 0.f;
#pragma unroll
        for (int w = 0; w < 4; w++) {
            float2 p = red[tid * 4 + w];
            float mn = fmaxf(m, p.x);
            s = s * __expf(m - mn) + p.y * __expf(p.x - mn);
            m = mn;
        }
        g_pmax[(size_t)(rowBase + tid) * NCHUNK + chunk] = m;
        g_psum[(size_t)(rowBase + tid) * NCHUNK + chunk] = s;
    }
}

// ---------------------------------------------------------------------------
// Kernel 3: fused detect + target + LSE + final mean. One warp per row;
// last block (atomic counter) reduces the 128 block partials deterministically.
// ---------------------------------------------------------------------------
__global__ void tail_kernel(const float* __restrict__ emb,
                            const float* __restrict__ wgt,
                            const void* __restrict__ lbl,
                            float* __restrict__ out) {
    __shared__ float sh[8];
    __shared__ int   lastFlag;

    // label dtype detection: 256 threads sample first 2KB (in-bounds for both)
    long long probe = ((const long long*)lbl)[threadIdx.x];
    int ok = (probe >= 0 && probe < (long long)NCLS) ? 1 : 0;
    int is64 = __syncthreads_and(ok);

    int wid  = threadIdx.x >> 5;
    int lane = threadIdx.x & 31;
    int row  = blockIdx.x * 8 + wid;

    long long lab = is64 ? ((const long long*)lbl)[row]
                         : (long long)((const int*)lbl)[row];

    // fp32-exact target dot (W row norm from g_inv_w, filled by prep paths)
    const float4* e4 = (const float4*)(emb + (size_t)row * DIM);
    const float4* w4 = (const float4*)(wgt + (size_t)lab * DIM);
    float td = 0.f;
#pragma unroll
    for (int i = 0; i < 4; i++) {
        float4 a = e4[lane + i * 32];
        float4 b = w4[lane + i * 32];
        td = fmaf(a.x, b.x, td);
        td = fmaf(a.y, b.y, td);
        td = fmaf(a.z, b.z, td);
        td = fmaf(a.w, b.w, td);
    }
#pragma unroll
    for (int o = 16; o; o >>= 1) td += __shfl_xor_sync(0xFFFFFFFFu, td, o);

    // LSE merge over chunk partials
    float m = -1e30f, s = 0.f;
    const float* pm_base = &g_pmax[(size_t)row * NCHUNK];
    const float* ps_base = &g_psum[(size_t)row * NCHUNK];
    for (int ch = lane; ch < NCHUNK; ch += 32) {
        float pm = pm_base[ch];
        float ps = ps_base[ch];
        float mn = fmaxf(m, pm);
        s = s * __expf(m - mn) + ps * __expf(pm - mn);
        m = mn;
    }
#pragma unroll
    for (int o = 16; o; o >>= 1) {
        float om = __shfl_xor_sync(0xFFFFFFFFu, m, o);
        float os = __shfl_xor_sync(0xFFFFFFFFu, s, o);
        float mn = fmaxf(m, om);
        s = s * __expf(m - mn) + os * __expf(om - mn);
        m = mn;
    }

    if (lane == 0) {
        float t = td * g_inv_e[row] * g_inv_w[lab];
        t = fminf(1.f, fmaxf(-1.f, t));
        float th = acosf(t);
        float tn = cosf(fminf(th + MARGIN, PI_F)) * SCALE;
        float to = t * SCALE;
        float s2 = s + __expf(tn - m) - __expf(to - m);
        s2 = fmaxf(s2, 1e-30f);
        sh[wid] = m + logf(s2) - tn;
    }
    __syncthreads();

    if (threadIdx.x == 0) {
        float ps = 0.f;
#pragma unroll
        for (int i = 0; i < 8; i++) ps += sh[i];
        g_part[blockIdx.x] = ps;
        __threadfence();
        int prev = atomicAdd(&g_done, 1);
        lastFlag = (prev == (BATCH / 8) - 1) ? 1 : 0;
    }
    __syncthreads();

    if (lastFlag && threadIdx.x == 0) {
        float total = 0.f;
        for (int i = 0; i < BATCH / 8; i++) total += g_part[i];   // fixed order
        out[0] = total / (float)BATCH;
    }
}

// ---------------------------------------------------------------------------
extern "C" void kernel_launch(void* const* d_in, const int* in_sizes, int n_in,
                              void* d_out, int out_size) {
    (void)in_sizes; (void)n_in; (void)out_size;
    const float* emb = (const float*)d_in[0];
    const float* wgt = (const float*)d_in[1];
    const void*  lbl = d_in[2];
    float* out       = (float*)d_out;

    cudaFuncSetAttribute(gemm_mma_kernel,
                         cudaFuncAttributeMaxDynamicSharedMemorySize, SM_TOTAL);

    // initial prep: embeddings (1024 rows) + first LA chunks of W (8192 rows)
    int totalRows = BATCH + LA * BN;
    prep_kernel<<<(totalRows + 7) / 8, 256>>>(emb, wgt);

    dim3 grid(BATCH / BM, NCHUNK);   // x = row-block (fast), y = chunk
    gemm_mma_kernel<<<grid, 256, SM_TOTAL>>>(wgt);

    tail_kernel<<<BATCH / 8, 256>>>(emb, wgt, lbl, out);
}